// round 11
// baseline (speedup 1.0000x reference)
#include <cuda_runtime.h>

// Fully fused UpFIRDn2d, reordered dn-convs: Hup -> Vup+leaky+Vdn (fused, per
// column, zero recompute within a unit) -> Hdn.
// Polyphase up taps (pl=5 correlation):
//   y[2m]   = sum e[k]*x[m-3+k] (k=0..6)
//   y[2m+1] = sum o[k]*x[m-2+k] (k=0..5)
// In t1-row space: a[2i] = sum_j o[j]*t1[i+j] (j<6); a[2i+1] = sum_j e[j]*t1[i+j] (j<7)
// Vdn: t2b[Yl] = sum_{k<12} dn[k] * leaky(a[2Yl+k])
// Upsampled coords valid only on [0,256) per axis; outside -> 0.
//
// SMEM: region A [0,2432): s_x (43 x p46 = 1978) S0/S1; t2b (32 x p76 = 2432) S2/S3
//       region B [2432,5700): t1 (43 x p76 = 3268) S1/S2
// Total 5700 floats = 22.8 KB.

#define NTHR 256
#define PX 46
#define PT 76
#define T1_OFF 2432
#define SM_TOTAL (2432 + 43 * PT)   // 5700 floats

typedef unsigned long long u64;

__device__ __forceinline__ u64 pk2(float lo, float hi) {
    u64 r; asm("mov.b64 %0, {%1, %2};" : "=l"(r) : "f"(lo), "f"(hi)); return r;
}
__device__ __forceinline__ void upk2(u64 v, float& lo, float& hi) {
    asm("mov.b64 {%0, %1}, %2;" : "=f"(lo), "=f"(hi) : "l"(v));
}
__device__ __forceinline__ u64 ffma2(u64 a, u64 b, u64 c) {
    u64 d; asm("fma.rn.f32x2 %0, %1, %2, %3;" : "=l"(d) : "l"(a), "l"(b), "l"(c)); return d;
}

__global__ __launch_bounds__(NTHR, 5)
void upfirdn2d_fused_kernel(const float* __restrict__ x,
                            const float* __restrict__ bias,
                            const float* __restrict__ fup,
                            const float* __restrict__ fdn,
                            float* __restrict__ out)
{
    __shared__ float smem[SM_TOTAL];
    float* s_x  = smem;              // pitch 46 (S0-S1)
    float* s_t2 = smem;              // t2b 32 x p76 (S2-S3), aliases s_x
    float* s_t1 = smem + T1_OFF;     // pitch 76 (S1-S2)

    const int tid = threadIdx.x;
    const int bc  = blockIdx.y;
    const int Y0  = (blockIdx.x >> 2) * 32;
    const int X0  = (blockIdx.x & 3)  * 32;
    const bool x_int = (X0 != 0) && (X0 != 96);
    const bool y_int = (Y0 != 0) && (Y0 != 96);

    // polyphase up taps
    float e[7], o[6];
    {
        float up[12];
        #pragma unroll
        for (int k = 0; k < 12; k++) up[k] = fup[k];
        e[0] = up[0]; e[6] = up[11];
        #pragma unroll
        for (int j = 1; j < 6; j++) e[j] = up[2*j - 1] + up[2*j];
        #pragma unroll
        for (int j = 0; j < 6; j++) o[j] = up[2*j] + up[2*j + 1];
    }
    const float bv = bias[bc & 63];
    const float* xin = x + (size_t)bc * (130 * 130);

    // ---- S0: input tile + halo (43 x 44), bias, zero pad ----
    {
        const int lane = tid & 31, w = tid >> 5;
        if (x_int && y_int) {
            #pragma unroll
            for (int rr = 0; rr < 6; rr++) {
                int r = w + 8 * rr;
                if (r < 43) {
                    const float* src = xin + (Y0 - 4 + r) * 130 + (X0 - 5);
                    float* dst = s_x + r * PX;
                    #pragma unroll
                    for (int ci = 0; ci < 2; ci++) {
                        int cc = lane + 32 * ci;
                        if (cc < 44) dst[cc] = src[cc] + bv;
                    }
                }
            }
        } else {
            #pragma unroll
            for (int rr = 0; rr < 6; rr++) {
                int r = w + 8 * rr;
                if (r < 43) {
                    int gy = Y0 - 5 + r;
                    bool rowok = (unsigned)gy < 128u;
                    const float* src = xin + (gy + 1) * 130 + (X0 - 5);
                    float* dst = s_x + r * PX;
                    #pragma unroll
                    for (int ci = 0; ci < 2; ci++) {
                        int cc = lane + 32 * ci;
                        if (cc < 44) {
                            int gx = X0 - 6 + cc;
                            float v = 0.0f;
                            if (rowok && (unsigned)gx < 128u) v = src[cc] + bv;
                            dst[cc] = v;
                        }
                    }
                }
            }
        }
    }
    __syncthreads();

    // ---- S1: horizontal polyphase up -> t1[43][74] ----
    #pragma unroll
    for (int it = 0; it < 2; it++) {
        int u = tid + 256 * it;
        if (u < 43 * 9) {
            int r  = u / 9;
            int tp = u - r * 9;
            const float2* row2 = reinterpret_cast<const float2*>(s_x + r * PX + 4 * tp);
            float2 q0 = row2[0], q1 = row2[1], q2 = row2[2],
                   q3 = row2[3], q4 = row2[4], q5 = row2[5];
            float xw[12] = {q0.x,q0.y,q1.x,q1.y,q2.x,q2.y,
                            q3.x,q3.y,q4.x,q4.y,q5.x,q5.y};
            float res[8];
            #pragma unroll
            for (int p = 0; p < 4; p++) {
                float vo = o[0]*xw[p+1] + o[1]*xw[p+2] + o[2]*xw[p+3]
                         + o[3]*xw[p+4] + o[4]*xw[p+5] + o[5]*xw[p+6];
                float ve = e[0]*xw[p+1] + e[1]*xw[p+2] + e[2]*xw[p+3] + e[3]*xw[p+4]
                         + e[4]*xw[p+5] + e[5]*xw[p+6] + e[6]*xw[p+7];
                if (!x_int) {
                    int gc = 2 * X0 - 5 + 8 * tp + 2 * p;
                    vo = ((unsigned)gc       < 256u) ? vo : 0.f;
                    ve = ((unsigned)(gc + 1) < 256u) ? ve : 0.f;
                }
                res[2*p] = vo; res[2*p + 1] = ve;
            }
            float* dst = s_t1 + r * PT + 8 * tp;
            *reinterpret_cast<float4*>(dst)     = make_float4(res[0],res[1],res[2],res[3]);
            *reinterpret_cast<float4*>(dst + 4) = make_float4(res[4],res[5],res[6],res[7]);
            if (tp == 8) {   // pair 36 -> t1 cols 72,73; window xw[5..11]
                float vo = o[0]*xw[5] + o[1]*xw[6] + o[2]*xw[7]
                         + o[3]*xw[8] + o[4]*xw[9] + o[5]*xw[10];
                float ve = e[0]*xw[5] + e[1]*xw[6] + e[2]*xw[7] + e[3]*xw[8]
                         + e[4]*xw[9] + e[5]*xw[10] + e[6]*xw[11];
                if (!x_int) {
                    int gc = 2 * X0 - 5 + 72;
                    vo = ((unsigned)gc       < 256u) ? vo : 0.f;
                    ve = ((unsigned)(gc + 1) < 256u) ? ve : 0.f;
                }
                *reinterpret_cast<float2*>(dst + 8) = make_float2(vo, ve);
            }
        }
    }

    // fold leaky gain sqrt(2) into up taps (sign test invariant under positive scale)
    {
        const float G = 1.41421356237309515f;
        #pragma unroll
        for (int k = 0; k < 7; k++) e[k] *= G;
        #pragma unroll
        for (int k = 0; k < 6; k++) o[k] *= G;
    }

    // dn taps (scalar; live through S2/S3)
    float dn[12];
    #pragma unroll
    for (int k = 0; k < 12; k++) dn[k] = fdn[k];
    __syncthreads();

    // ---- S2: fused Vup + leaky + Vdn -> t2b[32][74] ----
    // unit (q, col), q in 0..3: outputs Yl = 8q..8q+7 of column col.
    // Stream t1 rows 8q..8q+18 through 7-reg ring window; at step ii (i=8q+ii):
    //   a_o = a[2i] (o taps), a_e = a[2i+1] (e taps); leaky; scatter to acc[p]
    //   with taps dn[2(ii-p)], dn[2(ii-p)+1] for p in [ii-5, ii] ∩ [0,8).
    #pragma unroll
    for (int it = 0; it < 2; it++) {
        int u = tid + 256 * it;
        if (u < 296) {
            int q   = u / 74;
            int col = u - q * 74;
            const float* tc = s_t1 + (8 * q) * PT + col;
            float w[7];
            #pragma unroll
            for (int j = 0; j < 7; j++) w[j] = tc[j * PT];
            float acc[8] = {0,0,0,0,0,0,0,0};
            const int grb = 2 * Y0 - 5 + 16 * q;
            #pragma unroll
            for (int ii = 0; ii < 13; ii++) {
                // window invariant: w[(ii+j)%7] == t1[8q+ii+j][col], j=0..6
                float ao = o[0]*w[(ii)%7]   + o[1]*w[(ii+1)%7] + o[2]*w[(ii+2)%7]
                         + o[3]*w[(ii+3)%7] + o[4]*w[(ii+4)%7] + o[5]*w[(ii+5)%7];
                float ae = e[0]*w[(ii)%7]   + e[1]*w[(ii+1)%7] + e[2]*w[(ii+2)%7]
                         + e[3]*w[(ii+3)%7] + e[4]*w[(ii+4)%7] + e[5]*w[(ii+5)%7]
                         + e[6]*w[(ii+6)%7];
                if (!y_int) {
                    int gro = grb + 2 * ii;
                    ao = ((unsigned)gro       < 256u) ? ao : 0.f;
                    ae = ((unsigned)(gro + 1) < 256u) ? ae : 0.f;
                }
                ao = (ao >= 0.f) ? ao : 0.2f * ao;
                ae = (ae >= 0.f) ? ae : 0.2f * ae;
                #pragma unroll
                for (int p = 0; p < 8; p++) {
                    const int k2 = 2 * (ii - p);
                    if (k2 >= 0 && k2 < 12) {
                        acc[p] += dn[k2]     * ao;
                        acc[p] += dn[k2 + 1] * ae;
                    }
                }
                if (ii < 12) w[ii % 7] = tc[(ii + 7) * PT];
            }
            float* dst = s_t2 + (8 * q) * PT + col;
            #pragma unroll
            for (int p = 0; p < 8; p++) dst[p * PT] = acc[p];
        }
    }
    __syncthreads();

    // ---- S3: horizontal dn-conv, stride-2 -> out; packed f32x2, 8 outputs/unit ----
    // unit (t, Yl): outputs X = 8t..8t+7 of out row Y0+Yl; reads t2b[Yl][16t..16t+27].
    if (tid < 128) {
        int t  = tid >> 5;
        int Yl = tid & 31;
        u64 pdn[6];
        #pragma unroll
        for (int m = 0; m < 6; m++) pdn[m] = pk2(dn[2*m], dn[2*m + 1]);
        const float4* row = reinterpret_cast<const float4*>(s_t2 + Yl * PT + 16 * t);
        u64 facc[8] = {0,0,0,0,0,0,0,0};
        #pragma unroll
        for (int j = 0; j < 7; j++) {
            float4 qv = row[j];
            u64 pelA = pk2(qv.x, qv.y);
            u64 pelB = pk2(qv.z, qv.w);
            const int nA = 2 * j, nB = 2 * j + 1;
            #pragma unroll
            for (int qq = 0; qq < 8; qq++) {
                int mA = nA - qq;
                if (mA >= 0 && mA < 6) facc[qq] = ffma2(pdn[mA], pelA, facc[qq]);
                int mB = nB - qq;
                if (mB >= 0 && mB < 6) facc[qq] = ffma2(pdn[mB], pelB, facc[qq]);
            }
        }
        float acc[8];
        #pragma unroll
        for (int qq = 0; qq < 8; qq++) {
            float lo, hi; upk2(facc[qq], lo, hi);
            acc[qq] = lo + hi;
        }
        float* op = out + ((size_t)bc * 128 + (Y0 + Yl)) * 128 + X0 + 8 * t;
        *reinterpret_cast<float4*>(op)     = make_float4(acc[0],acc[1],acc[2],acc[3]);
        *reinterpret_cast<float4*>(op + 4) = make_float4(acc[4],acc[5],acc[6],acc[7]);
    }
}

extern "C" void kernel_launch(void* const* d_in, const int* in_sizes, int n_in,
                              void* d_out, int out_size)
{
    const float* x    = (const float*)d_in[0];   // (8,64,130,130) fp32
    const float* bias = (const float*)d_in[1];   // (64,) fp32
    const float* fup  = (const float*)d_in[2];   // (12,) fp32
    const float* fdn  = (const float*)d_in[3];   // (12,) fp32
    float* out = (float*)d_out;                  // (8,64,128,128) fp32

    dim3 grid(16, 512);
    upfirdn2d_fused_kernel<<<grid, NTHR>>>(x, bias, fup, fdn, out);
}

// round 12
// speedup vs baseline: 1.1709x; 1.1709x over previous
#include <cuda_runtime.h>

// Fully fused UpFIRDn2d (crop -> bias -> up2 -> sep FIR12 -> leaky*sqrt2 -> sep FIR12 -> dn2)
// Polyphase up taps (pl=5 correlation):
//   y[2m]   = sum e[k]*x[m-3+k] (k=0..6)
//   y[2m+1] = sum o[k]*x[m-2+k] (k=0..5)
// Upsampled coords valid only on [0,256) per axis; outside -> 0 (dn-conv pad).
// S3/S4 packed fp32x2 FMA. S1: 258 units (6-7 pairs each). S2: 185 units with a
// 7x float2 ring window streaming 8 row-pairs per column-pair.
//
// SMEM regions (floats), aliased by lifetime:
//   A [0,5624):     s_x (43 x p46 = 1978) S0/S1;  a (74 x p76 = 5624) S2/S3
//   B [5624,8892):  t1 (43 x p76 = 3268) S1/S2;  t2 (74 x p36 = 2664) S3/S4
// Total 8892 floats = 35.6 KB -> 6 CTAs = 213 KB <= 228 KB.

#define NTHR 256
#define PX 46
#define PT 76
#define P2 36
#define RB_OFF 5624
#define SM_TOTAL (5624 + 43 * PT)   // 8892 floats

typedef unsigned long long u64;

__device__ __forceinline__ u64 pk2(float lo, float hi) {
    u64 r; asm("mov.b64 %0, {%1, %2};" : "=l"(r) : "f"(lo), "f"(hi)); return r;
}
__device__ __forceinline__ void upk2(u64 v, float& lo, float& hi) {
    asm("mov.b64 {%0, %1}, %2;" : "=f"(lo), "=f"(hi) : "l"(v));
}
__device__ __forceinline__ u64 ffma2(u64 a, u64 b, u64 c) {
    u64 d; asm("fma.rn.f32x2 %0, %1, %2, %3;" : "=l"(d) : "l"(a), "l"(b), "l"(c)); return d;
}

__global__ __launch_bounds__(NTHR, 6)
void upfirdn2d_fused_kernel(const float* __restrict__ x,
                            const float* __restrict__ bias,
                            const float* __restrict__ fup,
                            const float* __restrict__ fdn,
                            float* __restrict__ out)
{
    __shared__ float smem[SM_TOTAL];
    float* s_x  = smem;              // pitch 46 (S0-S1)
    float* s_a  = smem;              // pitch 76 (S2-S3), aliases s_x
    float* s_t1 = smem + RB_OFF;     // pitch 76, 43 rows (S1-S2)
    float* s_t2 = smem + RB_OFF;     // pitch 36 (S3-S4), aliases t1

    const int tid = threadIdx.x;
    const int bc  = blockIdx.y;
    const int Y0  = (blockIdx.x >> 2) * 32;
    const int X0  = (blockIdx.x & 3)  * 32;
    const bool x_int = (X0 != 0) && (X0 != 96);
    const bool y_int = (Y0 != 0) && (Y0 != 96);

    // polyphase up taps
    float e[7], o[6];
    {
        float up[12];
        #pragma unroll
        for (int k = 0; k < 12; k++) up[k] = fup[k];
        e[0] = up[0]; e[6] = up[11];
        #pragma unroll
        for (int j = 1; j < 6; j++) e[j] = up[2*j - 1] + up[2*j];
        #pragma unroll
        for (int j = 0; j < 6; j++) o[j] = up[2*j] + up[2*j + 1];
    }
    const float bv = bias[bc & 63];
    const float* xin = x + (size_t)bc * (130 * 130);

    // ---- S0: input tile + halo (43 x 44), bias, zero pad ----
    {
        const int lane = tid & 31, w = tid >> 5;
        if (x_int && y_int) {
            #pragma unroll
            for (int rr = 0; rr < 6; rr++) {
                int r = w + 8 * rr;
                if (r < 43) {
                    const float* src = xin + (Y0 - 4 + r) * 130 + (X0 - 5);
                    float* dst = s_x + r * PX;
                    #pragma unroll
                    for (int ci = 0; ci < 2; ci++) {
                        int cc = lane + 32 * ci;
                        if (cc < 44) dst[cc] = src[cc] + bv;
                    }
                }
            }
        } else {
            #pragma unroll
            for (int rr = 0; rr < 6; rr++) {
                int r = w + 8 * rr;
                if (r < 43) {
                    int gy = Y0 - 5 + r;
                    bool rowok = (unsigned)gy < 128u;
                    const float* src = xin + (gy + 1) * 130 + (X0 - 5);
                    float* dst = s_x + r * PX;
                    #pragma unroll
                    for (int ci = 0; ci < 2; ci++) {
                        int cc = lane + 32 * ci;
                        if (cc < 44) {
                            int gx = X0 - 6 + cc;
                            float v = 0.0f;
                            if (rowok && (unsigned)gx < 128u) v = src[cc] + bv;
                            dst[cc] = v;
                        }
                    }
                }
            }
        }
    }
    __syncthreads();

    // ---- S1: horizontal polyphase up -> t1[43][74]; 258 units ----
    // unit (r, tp 0..5): pairs j = 6tp..6tp+5 (+pair 36 when tp==5);
    // window x cols 6tp..6tp+13 (7 float2); pair p: vo/ve from xw[p+1..p+7].
    #pragma unroll
    for (int it = 0; it < 2; it++) {
        int u = tid + 256 * it;
        if (u < 258) {
            int r  = u / 6;
            int tp = u - r * 6;
            const float2* row2 = reinterpret_cast<const float2*>(s_x + r * PX + 6 * tp);
            float xw[14];
            #pragma unroll
            for (int j = 0; j < 7; j++) {
                float2 q = row2[j];
                xw[2*j] = q.x; xw[2*j + 1] = q.y;
            }
            float res[14];
            #pragma unroll
            for (int p = 0; p < 7; p++) {
                if (p < 6 || tp == 5) {
                    float vo = o[0]*xw[p+1] + o[1]*xw[p+2] + o[2]*xw[p+3]
                             + o[3]*xw[p+4] + o[4]*xw[p+5] + o[5]*xw[p+6];
                    float ve = e[0]*xw[p+1] + e[1]*xw[p+2] + e[2]*xw[p+3] + e[3]*xw[p+4]
                             + e[4]*xw[p+5] + e[5]*xw[p+6] + e[6]*xw[p+7];
                    if (!x_int) {
                        int gc = 2 * X0 - 5 + 12 * tp + 2 * p;
                        vo = ((unsigned)gc       < 256u) ? vo : 0.f;
                        ve = ((unsigned)(gc + 1) < 256u) ? ve : 0.f;
                    }
                    res[2*p] = vo; res[2*p + 1] = ve;
                }
            }
            float* dst = s_t1 + r * PT + 12 * tp;
            *reinterpret_cast<float4*>(dst)     = make_float4(res[0],res[1],res[2],res[3]);
            *reinterpret_cast<float4*>(dst + 4) = make_float4(res[4],res[5],res[6],res[7]);
            *reinterpret_cast<float4*>(dst + 8) = make_float4(res[8],res[9],res[10],res[11]);
            if (tp == 5)
                *reinterpret_cast<float2*>(dst + 12) = make_float2(res[12], res[13]);
        }
    }

    // fold leaky gain sqrt(2) into up taps (sign test invariant under positive scale)
    {
        const float G = 1.41421356237309515f;
        #pragma unroll
        for (int k = 0; k < 7; k++) e[k] *= G;
        #pragma unroll
        for (int k = 0; k < 6; k++) o[k] *= G;
    }
    __syncthreads();

    // ---- S2: vertical polyphase up + leaky -> a[74][74]; 185 units, ring window ----
    // unit (g 0..4, ac2 0..36): col-pair 2ac2, row-pairs i = 8g..8g+7 (i<37).
    // Ring invariant at step p: w[(p+j)%7] == t1[8g+p+j][col-pair], j=0..6.
    {
        int u = tid;
        if (u < 185) {
            int g   = u / 37;
            int ac2 = u - g * 37;
            const float* base = s_t1 + (8 * g) * PT + 2 * ac2;
            float2 w[7];
            #pragma unroll
            for (int j = 0; j < 7; j++)
                w[j] = *reinterpret_cast<const float2*>(base + j * PT);
            float* adst = s_a + (16 * g) * PT + 2 * ac2;
            #pragma unroll
            for (int p = 0; p < 8; p++) {
                int i = 8 * g + p;
                if (i < 37) {
                    float vox = o[0]*w[(p)%7].x   + o[1]*w[(p+1)%7].x + o[2]*w[(p+2)%7].x
                              + o[3]*w[(p+3)%7].x + o[4]*w[(p+4)%7].x + o[5]*w[(p+5)%7].x;
                    float voy = o[0]*w[(p)%7].y   + o[1]*w[(p+1)%7].y + o[2]*w[(p+2)%7].y
                              + o[3]*w[(p+3)%7].y + o[4]*w[(p+4)%7].y + o[5]*w[(p+5)%7].y;
                    float vex = e[0]*w[(p)%7].x   + e[1]*w[(p+1)%7].x + e[2]*w[(p+2)%7].x
                              + e[3]*w[(p+3)%7].x + e[4]*w[(p+4)%7].x + e[5]*w[(p+5)%7].x
                              + e[6]*w[(p+6)%7].x;
                    float vey = e[0]*w[(p)%7].y   + e[1]*w[(p+1)%7].y + e[2]*w[(p+2)%7].y
                              + e[3]*w[(p+3)%7].y + e[4]*w[(p+4)%7].y + e[5]*w[(p+5)%7].y
                              + e[6]*w[(p+6)%7].y;
                    if (!y_int) {
                        int gr = 2 * Y0 - 5 + 2 * i;
                        bool ok0 = (unsigned)gr       < 256u;
                        bool ok1 = (unsigned)(gr + 1) < 256u;
                        vox = ok0 ? vox : 0.f;  voy = ok0 ? voy : 0.f;
                        vex = ok1 ? vex : 0.f;  vey = ok1 ? vey : 0.f;
                    }
                    float2 ro, re;
                    ro.x = (vox >= 0.f) ? vox : 0.2f * vox;
                    ro.y = (voy >= 0.f) ? voy : 0.2f * voy;
                    re.x = (vex >= 0.f) ? vex : 0.2f * vex;
                    re.y = (vey >= 0.f) ? vey : 0.2f * vey;
                    *reinterpret_cast<float2*>(adst + (2 * p)     * PT) = ro;
                    *reinterpret_cast<float2*>(adst + (2 * p + 1) * PT) = re;
                    if (p < 7 && i + 1 < 37)
                        w[p % 7] = *reinterpret_cast<const float2*>(base + (p + 7) * PT);
                }
            }
        }
    }
    __syncthreads();

    // dn taps as packed pairs: pdn[m] = (dn[2m], dn[2m+1])
    u64 pdn[6];
    #pragma unroll
    for (int m = 0; m < 6; m++) pdn[m] = pk2(fdn[2*m], fdn[2*m + 1]);

    // ---- S3: horizontal dn-conv, stride-2 -> t2[74][32]; packed f32x2 ----
    #pragma unroll
    for (int it = 0; it < 2; it++) {
        int u = tid + 256 * it;
        if (u < 4 * 74) {
            int t  = u / 74;
            int ar = u - t * 74;
            const float4* row = reinterpret_cast<const float4*>(s_a + ar * PT + 16 * t);
            u64 facc[8] = {0,0,0,0,0,0,0,0};
            #pragma unroll
            for (int j = 0; j < 7; j++) {
                float4 qv = row[j];
                u64 pelA = pk2(qv.x, qv.y);
                u64 pelB = pk2(qv.z, qv.w);
                const int nA = 2 * j, nB = 2 * j + 1;
                #pragma unroll
                for (int q = 0; q < 8; q++) {
                    int mA = nA - q;
                    if (mA >= 0 && mA < 6) facc[q] = ffma2(pdn[mA], pelA, facc[q]);
                    int mB = nB - q;
                    if (mB >= 0 && mB < 6) facc[q] = ffma2(pdn[mB], pelB, facc[q]);
                }
            }
            float acc[8];
            #pragma unroll
            for (int q = 0; q < 8; q++) {
                float lo, hi; upk2(facc[q], lo, hi);
                acc[q] = lo + hi;
            }
            float* dst = s_t2 + ar * P2 + 8 * t;
            *reinterpret_cast<float4*>(dst)     = make_float4(acc[0],acc[1],acc[2],acc[3]);
            *reinterpret_cast<float4*>(dst + 4) = make_float4(acc[4],acc[5],acc[6],acc[7]);
        }
    }
    __syncthreads();

    // ---- S4: vertical dn-conv, stride-2 -> out; packed f32x2, streamed loads ----
    if (tid < 128) {
        int cp = tid & 15;
        int yg = tid >> 4;
        u64 d2[12];
        #pragma unroll
        for (int m = 0; m < 6; m++) {
            float a_, b_; upk2(pdn[m], a_, b_);
            d2[2*m]     = pk2(a_, a_);
            d2[2*m + 1] = pk2(b_, b_);
        }
        const float* base = s_t2 + (8 * yg) * P2 + 2 * cp;
        u64 facc[4] = {0,0,0,0};
        #pragma unroll
        for (int j = 0; j < 18; j++) {
            u64 r = *reinterpret_cast<const u64*>(base + j * P2);
            #pragma unroll
            for (int q = 0; q < 4; q++) {
                const int k = j - 2 * q;
                if (k >= 0 && k < 12) facc[q] = ffma2(d2[k], r, facc[q]);
            }
        }
        float* op = out + ((size_t)bc * 128 + (Y0 + 4 * yg)) * 128 + X0 + 2 * cp;
        #pragma unroll
        for (int q = 0; q < 4; q++)
            *reinterpret_cast<u64*>(op + q * 128) = facc[q];
    }
}

extern "C" void kernel_launch(void* const* d_in, const int* in_sizes, int n_in,
                              void* d_out, int out_size)
{
    const float* x    = (const float*)d_in[0];   // (8,64,130,130) fp32
    const float* bias = (const float*)d_in[1];   // (64,) fp32
    const float* fup  = (const float*)d_in[2];   // (12,) fp32
    const float* fdn  = (const float*)d_in[3];   // (12,) fp32
    float* out = (float*)d_out;                  // (8,64,128,128) fp32

    dim3 grid(16, 512);
    upfirdn2d_fused_kernel<<<grid, NTHR>>>(x, bias, fup, fdn, out);
}

// round 13
// speedup vs baseline: 1.1757x; 1.0041x over previous
#include <cuda_runtime.h>

// Fully fused UpFIRDn2d (crop -> bias -> up2 -> sep FIR12 -> leaky*sqrt2 -> sep FIR12 -> dn2)
// Polyphase up taps (pl=5 correlation):
//   y[2m]   = sum e[k]*x[m-3+k] (k=0..6)
//   y[2m+1] = sum o[k]*x[m-2+k] (k=0..5)
// Upsampled coords valid only on [0,256) per axis; outside -> 0 (dn-conv pad).
// S0+S1 are warp-fused: rows are partitioned by warp, so S1 needs only
// __syncwarp() after S0 (one fewer block barrier; warps decouple on S0 latency).
// S3/S4 packed fp32x2 FMA.
//
// SMEM regions (floats), aliased by lifetime:
//   A [0,5624):     s_x (43 x p46 = 1978) S0/S1;  a (74 x p76 = 5624) S2/S3
//   B [5624,8892):  t1 (43 x p76 = 3268) S1/S2;  t2 (74 x p36 = 2664) S3/S4
// Total 8892 floats = 35.6 KB -> 6 CTAs = 213 KB <= 228 KB.

#define NTHR 256
#define PX 46
#define PT 76
#define P2 36
#define RB_OFF 5624
#define SM_TOTAL (5624 + 43 * PT)   // 8892 floats

typedef unsigned long long u64;

__device__ __forceinline__ u64 pk2(float lo, float hi) {
    u64 r; asm("mov.b64 %0, {%1, %2};" : "=l"(r) : "f"(lo), "f"(hi)); return r;
}
__device__ __forceinline__ void upk2(u64 v, float& lo, float& hi) {
    asm("mov.b64 {%0, %1}, %2;" : "=f"(lo), "=f"(hi) : "l"(v));
}
__device__ __forceinline__ u64 ffma2(u64 a, u64 b, u64 c) {
    u64 d; asm("fma.rn.f32x2 %0, %1, %2, %3;" : "=l"(d) : "l"(a), "l"(b), "l"(c)); return d;
}

__global__ __launch_bounds__(NTHR, 6)
void upfirdn2d_fused_kernel(const float* __restrict__ x,
                            const float* __restrict__ bias,
                            const float* __restrict__ fup,
                            const float* __restrict__ fdn,
                            float* __restrict__ out)
{
    __shared__ float smem[SM_TOTAL];
    float* s_x  = smem;              // pitch 46 (S0-S1)
    float* s_a  = smem;              // pitch 76 (S2-S3), aliases s_x
    float* s_t1 = smem + RB_OFF;     // pitch 76, 43 rows (S1-S2)
    float* s_t2 = smem + RB_OFF;     // pitch 36 (S3-S4), aliases t1

    const int tid  = threadIdx.x;
    const int lane = tid & 31;
    const int w    = tid >> 5;
    const int bc  = blockIdx.y;
    const int Y0  = (blockIdx.x >> 2) * 32;
    const int X0  = (blockIdx.x & 3)  * 32;
    const bool x_int = (X0 != 0) && (X0 != 96);
    const bool y_int = (Y0 != 0) && (Y0 != 96);

    // polyphase up taps
    float e[7], o[6];
    {
        float up[12];
        #pragma unroll
        for (int k = 0; k < 12; k++) up[k] = fup[k];
        e[0] = up[0]; e[6] = up[11];
        #pragma unroll
        for (int j = 1; j < 6; j++) e[j] = up[2*j - 1] + up[2*j];
        #pragma unroll
        for (int j = 0; j < 6; j++) o[j] = up[2*j] + up[2*j + 1];
    }
    const float bv = bias[bc & 63];
    const float* xin = x + (size_t)bc * (130 * 130);

    // row partition: warps 0-2 own 6 rows, warps 3-7 own 5 rows (43 total)
    const int r0    = (w < 3) ? 6 * w : 5 * w + 3;
    const int nrows = (w < 3) ? 6 : 5;

    // ---- S0 (warp-local): input rows r0..r0+nrows-1 + halo cols, bias, pad ----
    if (x_int && y_int) {
        #pragma unroll
        for (int rl = 0; rl < 6; rl++) {
            if (rl < nrows) {
                int r = r0 + rl;
                const float* src = xin + (Y0 - 4 + r) * 130 + (X0 - 5);
                float* dst = s_x + r * PX;
                dst[lane] = src[lane] + bv;
                if (lane < 12) dst[lane + 32] = src[lane + 32] + bv;
            }
        }
    } else {
        #pragma unroll
        for (int rl = 0; rl < 6; rl++) {
            if (rl < nrows) {
                int r = r0 + rl;
                int gy = Y0 - 5 + r;
                bool rowok = (unsigned)gy < 128u;
                const float* src = xin + (gy + 1) * 130 + (X0 - 5);
                float* dst = s_x + r * PX;
                #pragma unroll
                for (int ci = 0; ci < 2; ci++) {
                    int cc = lane + 32 * ci;
                    if (cc < 44) {
                        int gx = X0 - 6 + cc;
                        float v = 0.0f;
                        if (rowok && (unsigned)gx < 128u) v = src[cc] + bv;
                        dst[cc] = v;
                    }
                }
            }
        }
    }
    __syncwarp();

    // ---- S1 (warp-local): horizontal polyphase up -> t1 rows r0..r0+nrows-1 ----
    // unit (r, tp 0..5): pairs j = 6tp..6tp+5 (+pair 36 when tp==5);
    // window x cols 6tp..6tp+13 (7 float2); pair p: vo/ve from xw[p+1..p+7].
    {
        const int nu = nrows * 6;   // 30 or 36
        #pragma unroll
        for (int half = 0; half < 2; half++) {
            int ul = lane + 32 * half;
            if (ul < nu) {
                int rl = ul / 6;
                int tp = ul - rl * 6;
                int r  = r0 + rl;
                const float2* row2 = reinterpret_cast<const float2*>(s_x + r * PX + 6 * tp);
                float xw[14];
                #pragma unroll
                for (int j = 0; j < 7; j++) {
                    float2 q = row2[j];
                    xw[2*j] = q.x; xw[2*j + 1] = q.y;
                }
                float res[14];
                #pragma unroll
                for (int p = 0; p < 7; p++) {
                    if (p < 6 || tp == 5) {
                        float vo = o[0]*xw[p+1] + o[1]*xw[p+2] + o[2]*xw[p+3]
                                 + o[3]*xw[p+4] + o[4]*xw[p+5] + o[5]*xw[p+6];
                        float ve = e[0]*xw[p+1] + e[1]*xw[p+2] + e[2]*xw[p+3] + e[3]*xw[p+4]
                                 + e[4]*xw[p+5] + e[5]*xw[p+6] + e[6]*xw[p+7];
                        if (!x_int) {
                            int gc = 2 * X0 - 5 + 12 * tp + 2 * p;
                            vo = ((unsigned)gc       < 256u) ? vo : 0.f;
                            ve = ((unsigned)(gc + 1) < 256u) ? ve : 0.f;
                        }
                        res[2*p] = vo; res[2*p + 1] = ve;
                    }
                }
                float* dst = s_t1 + r * PT + 12 * tp;
                *reinterpret_cast<float4*>(dst)     = make_float4(res[0],res[1],res[2],res[3]);
                *reinterpret_cast<float4*>(dst + 4) = make_float4(res[4],res[5],res[6],res[7]);
                *reinterpret_cast<float4*>(dst + 8) = make_float4(res[8],res[9],res[10],res[11]);
                if (tp == 5)
                    *reinterpret_cast<float2*>(dst + 12) = make_float2(res[12], res[13]);
            }
        }
    }

    // fold leaky gain sqrt(2) into up taps (sign test invariant under positive scale)
    {
        const float G = 1.41421356237309515f;
        #pragma unroll
        for (int k = 0; k < 7; k++) e[k] *= G;
        #pragma unroll
        for (int k = 0; k < 6; k++) o[k] *= G;
    }
    __syncthreads();

    // ---- S2: vertical polyphase up + leaky -> a[74][74]; 185 units, ring window ----
    // unit (g 0..4, ac2 0..36): col-pair 2ac2, row-pairs i = 8g..8g+7 (i<37).
    // Ring invariant at step p: w[(p+j)%7] == t1[8g+p+j][col-pair], j=0..6.
    {
        int u = tid;
        if (u < 185) {
            int g   = u / 37;
            int ac2 = u - g * 37;
            const float* base = s_t1 + (8 * g) * PT + 2 * ac2;
            float2 wv[7];
            #pragma unroll
            for (int j = 0; j < 7; j++)
                wv[j] = *reinterpret_cast<const float2*>(base + j * PT);
            float* adst = s_a + (16 * g) * PT + 2 * ac2;
            #pragma unroll
            for (int p = 0; p < 8; p++) {
                int i = 8 * g + p;
                if (i < 37) {
                    float vox = o[0]*wv[(p)%7].x   + o[1]*wv[(p+1)%7].x + o[2]*wv[(p+2)%7].x
                              + o[3]*wv[(p+3)%7].x + o[4]*wv[(p+4)%7].x + o[5]*wv[(p+5)%7].x;
                    float voy = o[0]*wv[(p)%7].y   + o[1]*wv[(p+1)%7].y + o[2]*wv[(p+2)%7].y
                              + o[3]*wv[(p+3)%7].y + o[4]*wv[(p+4)%7].y + o[5]*wv[(p+5)%7].y;
                    float vex = e[0]*wv[(p)%7].x   + e[1]*wv[(p+1)%7].x + e[2]*wv[(p+2)%7].x
                              + e[3]*wv[(p+3)%7].x + e[4]*wv[(p+4)%7].x + e[5]*wv[(p+5)%7].x
                              + e[6]*wv[(p+6)%7].x;
                    float vey = e[0]*wv[(p)%7].y   + e[1]*wv[(p+1)%7].y + e[2]*wv[(p+2)%7].y
                              + e[3]*wv[(p+3)%7].y + e[4]*wv[(p+4)%7].y + e[5]*wv[(p+5)%7].y
                              + e[6]*wv[(p+6)%7].y;
                    if (!y_int) {
                        int gr = 2 * Y0 - 5 + 2 * i;
                        bool ok0 = (unsigned)gr       < 256u;
                        bool ok1 = (unsigned)(gr + 1) < 256u;
                        vox = ok0 ? vox : 0.f;  voy = ok0 ? voy : 0.f;
                        vex = ok1 ? vex : 0.f;  vey = ok1 ? vey : 0.f;
                    }
                    float2 ro, re;
                    ro.x = (vox >= 0.f) ? vox : 0.2f * vox;
                    ro.y = (voy >= 0.f) ? voy : 0.2f * voy;
                    re.x = (vex >= 0.f) ? vex : 0.2f * vex;
                    re.y = (vey >= 0.f) ? vey : 0.2f * vey;
                    *reinterpret_cast<float2*>(adst + (2 * p)     * PT) = ro;
                    *reinterpret_cast<float2*>(adst + (2 * p + 1) * PT) = re;
                    if (p < 7 && i + 1 < 37)
                        wv[p % 7] = *reinterpret_cast<const float2*>(base + (p + 7) * PT);
                }
            }
        }
    }
    __syncthreads();

    // dn taps as packed pairs: pdn[m] = (dn[2m], dn[2m+1])
    u64 pdn[6];
    #pragma unroll
    for (int m = 0; m < 6; m++) pdn[m] = pk2(fdn[2*m], fdn[2*m + 1]);

    // ---- S3: horizontal dn-conv, stride-2 -> t2[74][32]; packed f32x2 ----
    #pragma unroll
    for (int it = 0; it < 2; it++) {
        int u = tid + 256 * it;
        if (u < 4 * 74) {
            int t  = u / 74;
            int ar = u - t * 74;
            const float4* row = reinterpret_cast<const float4*>(s_a + ar * PT + 16 * t);
            u64 facc[8] = {0,0,0,0,0,0,0,0};
            #pragma unroll
            for (int j = 0; j < 7; j++) {
                float4 qv = row[j];
                u64 pelA = pk2(qv.x, qv.y);
                u64 pelB = pk2(qv.z, qv.w);
                const int nA = 2 * j, nB = 2 * j + 1;
                #pragma unroll
                for (int q = 0; q < 8; q++) {
                    int mA = nA - q;
                    if (mA >= 0 && mA < 6) facc[q] = ffma2(pdn[mA], pelA, facc[q]);
                    int mB = nB - q;
                    if (mB >= 0 && mB < 6) facc[q] = ffma2(pdn[mB], pelB, facc[q]);
                }
            }
            float acc[8];
            #pragma unroll
            for (int q = 0; q < 8; q++) {
                float lo, hi; upk2(facc[q], lo, hi);
                acc[q] = lo + hi;
            }
            float* dst = s_t2 + ar * P2 + 8 * t;
            *reinterpret_cast<float4*>(dst)     = make_float4(acc[0],acc[1],acc[2],acc[3]);
            *reinterpret_cast<float4*>(dst + 4) = make_float4(acc[4],acc[5],acc[6],acc[7]);
        }
    }
    __syncthreads();

    // ---- S4: vertical dn-conv, stride-2 -> out; packed f32x2, streamed loads ----
    if (tid < 128) {
        int cp = tid & 15;
        int yg = tid >> 4;
        u64 d2[12];
        #pragma unroll
        for (int m = 0; m < 6; m++) {
            float a_, b_; upk2(pdn[m], a_, b_);
            d2[2*m]     = pk2(a_, a_);
            d2[2*m + 1] = pk2(b_, b_);
        }
        const float* base = s_t2 + (8 * yg) * P2 + 2 * cp;
        u64 facc[4] = {0,0,0,0};
        #pragma unroll
        for (int j = 0; j < 18; j++) {
            u64 r = *reinterpret_cast<const u64*>(base + j * P2);
            #pragma unroll
            for (int q = 0; q < 4; q++) {
                const int k = j - 2 * q;
                if (k >= 0 && k < 12) facc[q] = ffma2(d2[k], r, facc[q]);
            }
        }
        float* op = out + ((size_t)bc * 128 + (Y0 + 4 * yg)) * 128 + X0 + 2 * cp;
        #pragma unroll
        for (int q = 0; q < 4; q++)
            *reinterpret_cast<u64*>(op + q * 128) = facc[q];
    }
}

extern "C" void kernel_launch(void* const* d_in, const int* in_sizes, int n_in,
                              void* d_out, int out_size)
{
    const float* x    = (const float*)d_in[0];   // (8,64,130,130) fp32
    const float* bias = (const float*)d_in[1];   // (64,) fp32
    const float* fup  = (const float*)d_in[2];   // (12,) fp32
    const float* fdn  = (const float*)d_in[3];   // (12,) fp32
    float* out = (float*)d_out;                  // (8,64,128,128) fp32

    dim3 grid(16, 512);
    upfirdn2d_fused_kernel<<<grid, NTHR>>>(x, bias, fup, fdn, out);
}

// round 14
// speedup vs baseline: 1.2105x; 1.0296x over previous
#include <cuda_runtime.h>

// Fully fused UpFIRDn2d (crop -> bias -> up2 -> sep FIR12 -> leaky*sqrt2 -> sep FIR12 -> dn2)
// Tile: 32 rows x 64 cols of output per block; 512 threads; dynamic smem 65.5 KB.
// Polyphase up taps (pl=5 correlation):
//   y[2m]   = sum e[k]*x[m-3+k] (k=0..6)
//   y[2m+1] = sum o[k]*x[m-2+k] (k=0..5)
// Upsampled coords valid only on [0,256) per axis; outside -> 0 (dn-conv pad).
// All x-tiles are edge tiles (X0 in {0,64}); y edge only for Y0 in {0,96}.
// S0+S1 warp-fused (row partition over 16 warps, __syncwarp only).
// S3/S4 packed fp32x2 FMA.
//
// SMEM regions (floats), aliased by lifetime:
//   A [0,10360):      s_x (43 x p78 = 3354) S0/S1;  a (74 x p140 = 10360) S2/S3
//   B [10360,16380):  t1 (43 x p140 = 6020) S1/S2;  t2 (74 x p68 = 5032) S3/S4
// Total 16380 floats = 65520 B -> 3 CTAs = 196.6 KB <= 228 KB.

#define NTHR 512
#define PX 78
#define PT 140
#define P2 68
#define RB_OFF 10360
#define SM_FLOATS 16380
#define SM_BYTES (SM_FLOATS * 4)

typedef unsigned long long u64;

__device__ __forceinline__ u64 pk2(float lo, float hi) {
    u64 r; asm("mov.b64 %0, {%1, %2};" : "=l"(r) : "f"(lo), "f"(hi)); return r;
}
__device__ __forceinline__ void upk2(u64 v, float& lo, float& hi) {
    asm("mov.b64 {%0, %1}, %2;" : "=f"(lo), "=f"(hi) : "l"(v));
}
__device__ __forceinline__ u64 ffma2(u64 a, u64 b, u64 c) {
    u64 d; asm("fma.rn.f32x2 %0, %1, %2, %3;" : "=l"(d) : "l"(a), "l"(b), "l"(c)); return d;
}

__global__ __launch_bounds__(NTHR, 3)
void upfirdn2d_fused_kernel(const float* __restrict__ x,
                            const float* __restrict__ bias,
                            const float* __restrict__ fup,
                            const float* __restrict__ fdn,
                            float* __restrict__ out)
{
    extern __shared__ float smem[];
    float* s_x  = smem;              // 43 x p78 (S0-S1)
    float* s_a  = smem;              // 74 x p140 (S2-S3), aliases s_x
    float* s_t1 = smem + RB_OFF;     // 43 x p140 (S1-S2)
    float* s_t2 = smem + RB_OFF;     // 74 x p68 (S3-S4), aliases t1

    const int tid  = threadIdx.x;
    const int lane = tid & 31;
    const int w    = tid >> 5;       // 0..15
    const int bc   = blockIdx.y;
    const int Y0   = (blockIdx.x >> 1) * 32;
    const int X0   = (blockIdx.x & 1) * 64;
    const bool y_int = (Y0 != 0) && (Y0 != 96);

    // polyphase up taps
    float e[7], o[6];
    {
        float up[12];
        #pragma unroll
        for (int k = 0; k < 12; k++) up[k] = fup[k];
        e[0] = up[0]; e[6] = up[11];
        #pragma unroll
        for (int j = 1; j < 6; j++) e[j] = up[2*j - 1] + up[2*j];
        #pragma unroll
        for (int j = 0; j < 6; j++) o[j] = up[2*j] + up[2*j + 1];
    }
    const float bv = bias[bc & 63];
    const float* xin = x + (size_t)bc * (130 * 130);

    // row partition over 16 warps: warps 0-10 own 3 rows, 11-15 own 2 (43 total)
    const int r0    = (w < 11) ? 3 * w : 2 * w + 11;
    const int nrows = (w < 11) ? 3 : 2;

    // ---- S0 (warp-local): input rows + halo (cols 0..75), bias, zero pad ----
    #pragma unroll
    for (int rl = 0; rl < 3; rl++) {
        if (rl < nrows) {
            int r  = r0 + rl;
            int gy = Y0 - 5 + r;
            bool rowok = (unsigned)gy < 128u;
            const float* src = xin + (gy + 1) * 130 + (X0 - 5);
            float* dst = s_x + r * PX;
            #pragma unroll
            for (int ci = 0; ci < 3; ci++) {
                int cc = lane + 32 * ci;
                if (cc < 76) {
                    int gx = X0 - 6 + cc;
                    float v = 0.0f;
                    if (rowok && (unsigned)gx < 128u) v = src[cc] + bv;
                    dst[cc] = v;
                }
            }
        }
    }
    __syncwarp();

    // ---- S1 (warp-local): horizontal polyphase up -> t1[43][138] ----
    // unit (r, tp 0..11): pairs j = 6tp..6tp+5 (tp=11: only 3 pairs, 66..68);
    // window x cols 6tp..6tp+13 (7 float2; tail loads overshoot harmlessly).
    {
        const int nu = nrows * 12;  // 36 or 24
        #pragma unroll
        for (int half = 0; half < 2; half++) {
            int ul = lane + 32 * half;
            if (ul < nu) {
                int rl = ul / 12;
                int tp = ul - rl * 12;
                int r  = r0 + rl;
                const float2* row2 = reinterpret_cast<const float2*>(s_x + r * PX + 6 * tp);
                float xw[14];
                #pragma unroll
                for (int j = 0; j < 7; j++) {
                    float2 q = row2[j];
                    xw[2*j] = q.x; xw[2*j + 1] = q.y;
                }
                float res[12];
                #pragma unroll
                for (int p = 0; p < 6; p++) {
                    if (tp < 11 || p < 3) {
                        float vo = o[0]*xw[p+1] + o[1]*xw[p+2] + o[2]*xw[p+3]
                                 + o[3]*xw[p+4] + o[4]*xw[p+5] + o[5]*xw[p+6];
                        float ve = e[0]*xw[p+1] + e[1]*xw[p+2] + e[2]*xw[p+3] + e[3]*xw[p+4]
                                 + e[4]*xw[p+5] + e[5]*xw[p+6] + e[6]*xw[p+7];
                        int gc = 2 * X0 - 5 + 12 * tp + 2 * p;
                        vo = ((unsigned)gc       < 256u) ? vo : 0.f;
                        ve = ((unsigned)(gc + 1) < 256u) ? ve : 0.f;
                        res[2*p] = vo; res[2*p + 1] = ve;
                    }
                }
                float* dst = s_t1 + r * PT + 12 * tp;
                if (tp < 11) {
                    *reinterpret_cast<float4*>(dst)     = make_float4(res[0],res[1],res[2],res[3]);
                    *reinterpret_cast<float4*>(dst + 4) = make_float4(res[4],res[5],res[6],res[7]);
                    *reinterpret_cast<float4*>(dst + 8) = make_float4(res[8],res[9],res[10],res[11]);
                } else {
                    *reinterpret_cast<float4*>(dst)     = make_float4(res[0],res[1],res[2],res[3]);
                    *reinterpret_cast<float2*>(dst + 4) = make_float2(res[4], res[5]);
                }
            }
        }
    }

    // fold leaky gain sqrt(2) into up taps (sign test invariant under positive scale)
    {
        const float G = 1.41421356237309515f;
        #pragma unroll
        for (int k = 0; k < 7; k++) e[k] *= G;
        #pragma unroll
        for (int k = 0; k < 6; k++) o[k] *= G;
    }
    __syncthreads();

    // ---- S2: vertical polyphase up + leaky -> a[74][138]; 345 units, ring window ----
    // unit (g 0..4, ac2 0..68): col-pair 2ac2, row-pairs i = 8g..8g+7 (i<37).
    // Ring invariant at step p: wv[(p+j)%7] == t1[8g+p+j][col-pair], j=0..6.
    if (tid < 345) {
        int g   = tid / 69;
        int ac2 = tid - g * 69;
        const float* base = s_t1 + (8 * g) * PT + 2 * ac2;
        float2 wv[7];
        #pragma unroll
        for (int j = 0; j < 7; j++)
            wv[j] = *reinterpret_cast<const float2*>(base + j * PT);
        float* adst = s_a + (16 * g) * PT + 2 * ac2;
        #pragma unroll
        for (int p = 0; p < 8; p++) {
            int i = 8 * g + p;
            if (i < 37) {
                float vox = o[0]*wv[(p)%7].x   + o[1]*wv[(p+1)%7].x + o[2]*wv[(p+2)%7].x
                          + o[3]*wv[(p+3)%7].x + o[4]*wv[(p+4)%7].x + o[5]*wv[(p+5)%7].x;
                float voy = o[0]*wv[(p)%7].y   + o[1]*wv[(p+1)%7].y + o[2]*wv[(p+2)%7].y
                          + o[3]*wv[(p+3)%7].y + o[4]*wv[(p+4)%7].y + o[5]*wv[(p+5)%7].y;
                float vex = e[0]*wv[(p)%7].x   + e[1]*wv[(p+1)%7].x + e[2]*wv[(p+2)%7].x
                          + e[3]*wv[(p+3)%7].x + e[4]*wv[(p+4)%7].x + e[5]*wv[(p+5)%7].x
                          + e[6]*wv[(p+6)%7].x;
                float vey = e[0]*wv[(p)%7].y   + e[1]*wv[(p+1)%7].y + e[2]*wv[(p+2)%7].y
                          + e[3]*wv[(p+3)%7].y + e[4]*wv[(p+4)%7].y + e[5]*wv[(p+5)%7].y
                          + e[6]*wv[(p+6)%7].y;
                if (!y_int) {
                    int gr = 2 * Y0 - 5 + 2 * i;
                    bool ok0 = (unsigned)gr       < 256u;
                    bool ok1 = (unsigned)(gr + 1) < 256u;
                    vox = ok0 ? vox : 0.f;  voy = ok0 ? voy : 0.f;
                    vex = ok1 ? vex : 0.f;  vey = ok1 ? vey : 0.f;
                }
                float2 ro, re;
                ro.x = (vox >= 0.f) ? vox : 0.2f * vox;
                ro.y = (voy >= 0.f) ? voy : 0.2f * voy;
                re.x = (vex >= 0.f) ? vex : 0.2f * vex;
                re.y = (vey >= 0.f) ? vey : 0.2f * vey;
                *reinterpret_cast<float2*>(adst + (2 * p)     * PT) = ro;
                *reinterpret_cast<float2*>(adst + (2 * p + 1) * PT) = re;
                if (p < 7 && i + 1 < 37)
                    wv[p % 7] = *reinterpret_cast<const float2*>(base + (p + 7) * PT);
            }
        }
    }
    __syncthreads();

    // dn taps as packed pairs: pdn[m] = (dn[2m], dn[2m+1])
    u64 pdn[6];
    #pragma unroll
    for (int m = 0; m < 6; m++) pdn[m] = pk2(fdn[2*m], fdn[2*m + 1]);

    // ---- S3: horizontal dn-conv, stride-2 -> t2[74][64]; packed f32x2 ----
    // unit (t 0..7, ar 0..73): outputs X = 8t..8t+7; reads a[ar][16t..16t+27]
    // as 7 float4 (cols 138-139 loaded but never accumulated).
    #pragma unroll
    for (int it = 0; it < 2; it++) {
        int u = tid + 512 * it;
        if (u < 8 * 74) {
            int t  = u / 74;
            int ar = u - t * 74;
            const float4* row = reinterpret_cast<const float4*>(s_a + ar * PT + 16 * t);
            u64 facc[8] = {0,0,0,0,0,0,0,0};
            #pragma unroll
            for (int j = 0; j < 7; j++) {
                float4 qv = row[j];
                u64 pelA = pk2(qv.x, qv.y);
                u64 pelB = pk2(qv.z, qv.w);
                const int nA = 2 * j, nB = 2 * j + 1;
                #pragma unroll
                for (int q = 0; q < 8; q++) {
                    int mA = nA - q;
                    if (mA >= 0 && mA < 6) facc[q] = ffma2(pdn[mA], pelA, facc[q]);
                    int mB = nB - q;
                    if (mB >= 0 && mB < 6) facc[q] = ffma2(pdn[mB], pelB, facc[q]);
                }
            }
            float acc[8];
            #pragma unroll
            for (int q = 0; q < 8; q++) {
                float lo, hi; upk2(facc[q], lo, hi);
                acc[q] = lo + hi;
            }
            float* dst = s_t2 + ar * P2 + 8 * t;
            *reinterpret_cast<float4*>(dst)     = make_float4(acc[0],acc[1],acc[2],acc[3]);
            *reinterpret_cast<float4*>(dst + 4) = make_float4(acc[4],acc[5],acc[6],acc[7]);
        }
    }
    __syncthreads();

    // ---- S4: vertical dn-conv, stride-2 -> out; packed f32x2, streamed loads ----
    // 256 active threads: cp = col-pair 0..31, yg = 0..7 (out rows 4yg..4yg+3).
    if (tid < 256) {
        int cp = tid & 31;
        int yg = tid >> 5;
        u64 d2[12];
        #pragma unroll
        for (int m = 0; m < 6; m++) {
            float a_, b_; upk2(pdn[m], a_, b_);
            d2[2*m]     = pk2(a_, a_);
            d2[2*m + 1] = pk2(b_, b_);
        }
        const float* base = s_t2 + (8 * yg) * P2 + 2 * cp;
        u64 facc[4] = {0,0,0,0};
        #pragma unroll
        for (int j = 0; j < 18; j++) {
            u64 r = *reinterpret_cast<const u64*>(base + j * P2);
            #pragma unroll
            for (int q = 0; q < 4; q++) {
                const int k = j - 2 * q;
                if (k >= 0 && k < 12) facc[q] = ffma2(d2[k], r, facc[q]);
            }
        }
        float* op = out + ((size_t)bc * 128 + (Y0 + 4 * yg)) * 128 + X0 + 2 * cp;
        #pragma unroll
        for (int q = 0; q < 4; q++)
            *reinterpret_cast<u64*>(op + q * 128) = facc[q];
    }
}

extern "C" void kernel_launch(void* const* d_in, const int* in_sizes, int n_in,
                              void* d_out, int out_size)
{
    const float* x    = (const float*)d_in[0];   // (8,64,130,130) fp32
    const float* bias = (const float*)d_in[1];   // (64,) fp32
    const float* fup  = (const float*)d_in[2];   // (12,) fp32
    const float* fdn  = (const float*)d_in[3];   // (12,) fp32
    float* out = (float*)d_out;                  // (8,64,128,128) fp32

    // capture-safe (not a stream op); idempotent, called every launch
    cudaFuncSetAttribute(upfirdn2d_fused_kernel,
                         cudaFuncAttributeMaxDynamicSharedMemorySize, SM_BYTES);

    dim3 grid(8, 512);   // 8 tiles (2x wide, 4x tall) per channel-image
    upfirdn2d_fused_kernel<<<grid, NTHR, SM_BYTES>>>(x, bias, fup, fdn, out);
}